// round 1
// baseline (speedup 1.0000x reference)
#include <cuda_runtime.h>
#include <cstdint>

// Problem constants (fixed by reference)
#define NMAX  100000
#define EMAX  1600000
#define DHID  128
#define DOUTK 64

// Scratch (static device globals; allocation is forbidden)
__device__ float g_dis[NMAX];            // deg^{-1/2}
__device__ float g_en [EMAX];            // edge_norm = dis[src]*dis[dst]
__device__ float g_h  [NMAX * DHID];     // current features
__device__ float g_t  [NMAX * DHID];     // h @ W
__device__ float g_agg[NMAX * DHID];     // scatter accumulator

// ---------------------------------------------------------------- utilities
__global__ void k_fill1(float* p, int n) {
    int i = blockIdx.x * blockDim.x + threadIdx.x;
    if (i < n) p[i] = 1.0f;
}

__global__ void k_zero4(float* p, int n4) {
    int i = blockIdx.x * blockDim.x + threadIdx.x;
    if (i < n4) reinterpret_cast<float4*>(p)[i] = make_float4(0.f, 0.f, 0.f, 0.f);
}

__global__ void k_deg(const int* __restrict__ dst, float* __restrict__ deg, int e) {
    int i = blockIdx.x * blockDim.x + threadIdx.x;
    if (i < e) atomicAdd(&deg[dst[i]], 1.0f);
}

__global__ void k_rsqrt(float* p, int n) {
    int i = blockIdx.x * blockDim.x + threadIdx.x;
    if (i < n) p[i] = rsqrtf(p[i]);
}

__global__ void k_edgenorm(const int* __restrict__ src, const int* __restrict__ dst,
                           const float* __restrict__ dis, float* __restrict__ en, int e) {
    int i = blockIdx.x * blockDim.x + threadIdx.x;
    if (i < e) en[i] = dis[src[i]] * dis[dst[i]];
}

// ---------------------------------------------------------------- GEMM
// A: [M,128] row-major, W: [128,COLS] row-major, out: [M,COLS].
// Block: 64 rows x COLS cols; threads = 64 * (COLS/32); each thread -> 32 cols of 1 row.
template <int COLS>
__global__ void k_gemm(const float* __restrict__ A, const float* __restrict__ W,
                       const float* __restrict__ bias, float* __restrict__ out, int M) {
    constexpr int ROWS = 64;
    constexpr int CG   = COLS / 32;
    __shared__ float Ws[32 * COLS];   // one K-chunk of W
    __shared__ float Hs[ROWS * 36];   // padded row stride 36 (float4-aligned, conflict-free)

    const int tid  = threadIdx.x;
    const int rl   = tid / CG;
    const int cg   = tid % CG;
    const int row0 = blockIdx.x * ROWS;

    float acc[32];
#pragma unroll
    for (int j = 0; j < 32; j++) acc[j] = 0.f;

    for (int kc = 0; kc < 4; kc++) {
        // W chunk: rows [kc*32, kc*32+32), all COLS columns (contiguous in W)
        for (int i = tid * 4; i < 32 * COLS; i += blockDim.x * 4)
            *reinterpret_cast<float4*>(&Ws[i]) =
                *reinterpret_cast<const float4*>(&W[kc * 32 * COLS + i]);
        // H chunk: 64 rows x 32 k-values
        for (int i = tid; i < ROWS * 8; i += blockDim.x) {
            int r = i >> 3, k4 = (i & 7) * 4;
            int gr = row0 + r;
            float4 v = (gr < M)
                ? *reinterpret_cast<const float4*>(&A[(size_t)gr * 128 + kc * 32 + k4])
                : make_float4(0.f, 0.f, 0.f, 0.f);
            *reinterpret_cast<float4*>(&Hs[r * 36 + k4]) = v;
        }
        __syncthreads();
#pragma unroll
        for (int k = 0; k < 32; k++) {
            float hv = Hs[rl * 36 + k];
#pragma unroll
            for (int j = 0; j < 32; j++)
                acc[j] += hv * Ws[k * COLS + cg * 32 + j];
        }
        __syncthreads();
    }

    int gr = row0 + rl;
    if (gr < M) {
#pragma unroll
        for (int j = 0; j < 32; j += 4) {
            float4 v;
            float b0 = bias ? bias[cg * 32 + j + 0] : 0.f;
            float b1 = bias ? bias[cg * 32 + j + 1] : 0.f;
            float b2 = bias ? bias[cg * 32 + j + 2] : 0.f;
            float b3 = bias ? bias[cg * 32 + j + 3] : 0.f;
            v.x = acc[j + 0] + b0;
            v.y = acc[j + 1] + b1;
            v.z = acc[j + 2] + b2;
            v.w = acc[j + 3] + b3;
            *reinterpret_cast<float4*>(&out[(size_t)gr * COLS + cg * 32 + j]) = v;
        }
    }
}

// ---------------------------------------------------------------- edge scatter
// agg[dst] += t[src] * en[e], vectorized 4-wide with red.global.add.v4.f32
template <int COLS>
__global__ void k_scatter(const float* __restrict__ t, const int* __restrict__ src,
                          const int* __restrict__ dst, const float* __restrict__ en,
                          float* __restrict__ agg, int E) {
    constexpr int TPE = COLS / 4;  // threads per edge
    int gid = blockIdx.x * blockDim.x + threadIdx.x;
    int e = gid / TPE;
    int p = gid % TPE;
    if (e >= E) return;
    int s = src[e], d = dst[e];
    float w = en[e];
    float4 v = *reinterpret_cast<const float4*>(&t[(size_t)s * COLS + p * 4]);
    v.x *= w; v.y *= w; v.z *= w; v.w *= w;
    float* a = &agg[(size_t)d * COLS + p * 4];
    asm volatile("red.global.add.v4.f32 [%0], {%1,%2,%3,%4};"
                 :: "l"(a), "f"(v.x), "f"(v.y), "f"(v.z), "f"(v.w) : "memory");
}

// ---------------------------------------------------------------- combine
// out = [relu](agg + t * dis^2 + b)
template <int COLS, bool RELU>
__global__ void k_combine(const float* __restrict__ agg, const float* __restrict__ t,
                          const float* __restrict__ dis, const float* __restrict__ bias,
                          float* __restrict__ out, int n) {
    constexpr int TPN = COLS / 4;
    int gid = blockIdx.x * blockDim.x + threadIdx.x;
    int node = gid / TPN;
    int c = (gid % TPN) * 4;
    if (node >= n) return;
    float ds = dis[node];
    float sn = ds * ds;
    float4 a  = *reinterpret_cast<const float4*>(&agg[(size_t)node * COLS + c]);
    float4 tv = *reinterpret_cast<const float4*>(&t  [(size_t)node * COLS + c]);
    float4 b  = *reinterpret_cast<const float4*>(&bias[c]);
    float4 r;
    r.x = a.x + tv.x * sn + b.x;
    r.y = a.y + tv.y * sn + b.y;
    r.z = a.z + tv.z * sn + b.z;
    r.w = a.w + tv.w * sn + b.w;
    if (RELU) {
        r.x = fmaxf(r.x, 0.f); r.y = fmaxf(r.y, 0.f);
        r.z = fmaxf(r.z, 0.f); r.w = fmaxf(r.w, 0.f);
    }
    *reinterpret_cast<float4*>(&out[(size_t)node * COLS + c]) = r;
}

// ---------------------------------------------------------------- pool
__global__ void k_pool(const float* __restrict__ h, const int* __restrict__ batch,
                       float* __restrict__ out, int n) {
    int gid = blockIdx.x * blockDim.x + threadIdx.x;
    int node = gid / 16;          // 64 cols / 4
    int c = (gid % 16) * 4;
    if (node >= n) return;
    int g = batch[node];
    float4 v = *reinterpret_cast<const float4*>(&h[(size_t)node * 64 + c]);
    float* a = &out[(size_t)g * 64 + c];
    asm volatile("red.global.add.v4.f32 [%0], {%1,%2,%3,%4};"
                 :: "l"(a), "f"(v.x), "f"(v.y), "f"(v.z), "f"(v.w) : "memory");
}

// ---------------------------------------------------------------- launch
extern "C" void kernel_launch(void* const* d_in, const int* in_sizes, int n_in,
                              void* d_out, int out_size) {
    const float* x     = (const float*)d_in[0];
    const int*   ei    = (const int*)  d_in[1];
    const int*   batch = (const int*)  d_in[2];
    const float* W_emb = (const float*)d_in[3];
    const float* b_emb = (const float*)d_in[4];
    const float* W1    = (const float*)d_in[5];
    const float* b1    = (const float*)d_in[6];
    const float* W2    = (const float*)d_in[7];
    const float* b2    = (const float*)d_in[8];
    const float* W3    = (const float*)d_in[9];
    const float* b3    = (const float*)d_in[10];

    const int n = in_sizes[2];       // N nodes (batch vector length)
    const int e = in_sizes[1] / 2;   // E edges
    const int* src = ei;
    const int* dst = ei + e;

    float *dis, *en, *h, *t, *agg;
    cudaGetSymbolAddress((void**)&dis, g_dis);
    cudaGetSymbolAddress((void**)&en,  g_en);
    cudaGetSymbolAddress((void**)&h,   g_h);
    cudaGetSymbolAddress((void**)&t,   g_t);
    cudaGetSymbolAddress((void**)&agg, g_agg);

    const int TB = 256;
    auto cdiv = [](long long a, long long b) { return (int)((a + b - 1) / b); };

    // Normalization prep
    k_fill1   <<<cdiv(n, TB), TB>>>(dis, n);
    k_deg     <<<cdiv(e, TB), TB>>>(dst, dis, e);
    k_rsqrt   <<<cdiv(n, TB), TB>>>(dis, n);
    k_edgenorm<<<cdiv(e, TB), TB>>>(src, dst, dis, en, e);

    // Embedding: h = x @ W_emb + b_emb
    k_gemm<128><<<cdiv(n, 64), 256>>>(x, W_emb, b_emb, h, n);

    // Layer 1: h = relu(gcn(h, W1, b1))
    k_gemm<128><<<cdiv(n, 64), 256>>>(h, W1, nullptr, t, n);
    k_zero4<<<cdiv((long long)n * 32, TB), TB>>>(agg, n * 32);
    k_scatter<128><<<cdiv((long long)e * 32, TB), TB>>>(t, src, dst, en, agg, e);
    k_combine<128, true><<<cdiv((long long)n * 32, TB), TB>>>(agg, t, dis, b1, h, n);

    // Layer 2: h = relu(gcn(h, W2, b2))
    k_gemm<128><<<cdiv(n, 64), 256>>>(h, W2, nullptr, t, n);
    k_zero4<<<cdiv((long long)n * 32, TB), TB>>>(agg, n * 32);
    k_scatter<128><<<cdiv((long long)e * 32, TB), TB>>>(t, src, dst, en, agg, e);
    k_combine<128, true><<<cdiv((long long)n * 32, TB), TB>>>(agg, t, dis, b2, h, n);

    // Layer 3: h = gcn(h, W3, b3)   (D_OUT = 64, no relu)
    k_gemm<64><<<cdiv(n, 64), 128>>>(h, W3, nullptr, t, n);
    k_zero4<<<cdiv((long long)n * 16, TB), TB>>>(agg, n * 16);
    k_scatter<64><<<cdiv((long long)e * 16, TB), TB>>>(t, src, dst, en, agg, e);
    k_combine<64, false><<<cdiv((long long)n * 16, TB), TB>>>(agg, t, dis, b3, h, n);

    // Global add pool over sorted graph ids
    k_zero4<<<cdiv(out_size / 4, TB), TB>>>((float*)d_out, out_size / 4);
    k_pool<<<cdiv((long long)n * 16, TB), TB>>>(h, batch, (float*)d_out, n);
}

// round 2
// speedup vs baseline: 1.7835x; 1.7835x over previous
#include <cuda_runtime.h>
#include <cstdint>

#define NMAX  100000
#define EMAX  1600000
#define DHID  128

// Scratch (static device globals; allocation is forbidden)
__device__ float g_dis[NMAX];              // deg^{-1/2} (with self loop)
__device__ int   g_deg [NMAX];
__device__ int   g_rowptr[NMAX + 1];
__device__ int   g_cursor[NMAX];
__device__ int   g_esrc[EMAX];             // src ids grouped by dst (CSR)
__device__ float g_h  [NMAX * DHID];       // current features
__device__ float g_t  [NMAX * DHID];       // tb = (h @ W) * dis[row]

// ---------------------------------------------------------------- prep
__global__ void k_zeroi(int* p, int n) {
    int i = blockIdx.x * blockDim.x + threadIdx.x;
    if (i < n) p[i] = 0;
}
__global__ void k_zero4(float* p, int n4) {
    int i = blockIdx.x * blockDim.x + threadIdx.x;
    if (i < n4) reinterpret_cast<float4*>(p)[i] = make_float4(0.f, 0.f, 0.f, 0.f);
}
__global__ void k_deg(const int* __restrict__ dst, int* __restrict__ deg, int e) {
    int i = blockIdx.x * blockDim.x + threadIdx.x;
    if (i < e) atomicAdd(&deg[dst[i]], 1);
}
__global__ void k_dis(const int* __restrict__ deg, float* __restrict__ dis, int n) {
    int i = blockIdx.x * blockDim.x + threadIdx.x;
    if (i < n) dis[i] = rsqrtf((float)deg[i] + 1.0f);
}

// Single-block exclusive scan over deg -> rowptr (and cursor copy).
__global__ void k_scan(const int* __restrict__ deg, int* __restrict__ rowptr,
                       int* __restrict__ cursor, int n) {
    __shared__ int wsum[32];
    __shared__ int s_carry;
    const int tid = threadIdx.x;          // 1024 threads
    const int lane = tid & 31, wid = tid >> 5;
    if (tid == 0) s_carry = 0;
    __syncthreads();
    for (int base = 0; base < n; base += 1024) {
        int i = base + tid;
        int v = (i < n) ? deg[i] : 0;
        int x = v;
#pragma unroll
        for (int o = 1; o < 32; o <<= 1) {
            int y = __shfl_up_sync(0xffffffffu, x, o);
            if (lane >= o) x += y;
        }
        if (lane == 31) wsum[wid] = x;
        __syncthreads();
        if (wid == 0) {
            int w = wsum[lane];
            int xx = w;
#pragma unroll
            for (int o = 1; o < 32; o <<= 1) {
                int y = __shfl_up_sync(0xffffffffu, xx, o);
                if (lane >= o) xx += y;
            }
            wsum[lane] = xx - w;  // exclusive warp offset
        }
        __syncthreads();
        int incl = x + wsum[wid];
        int excl = incl - v + s_carry;
        if (i < n) { rowptr[i] = excl; cursor[i] = excl; }
        __syncthreads();
        if (tid == 1023) s_carry += incl;
        __syncthreads();
    }
    if (tid == 0) rowptr[n] = s_carry;
}

__global__ void k_permute(const int* __restrict__ src, const int* __restrict__ dst,
                          int* __restrict__ cursor, int* __restrict__ esrc, int e) {
    int i = blockIdx.x * blockDim.x + threadIdx.x;
    if (i < e) {
        int pos = atomicAdd(&cursor[dst[i]], 1);
        esrc[pos] = src[i];
    }
}

// ---------------------------------------------------------------- GEMM
// A: [M,128] row-major, W: [128,COLS] row-major, out: [M,COLS].
// Block: 64 rows x COLS cols; each thread -> 32 cols of 1 row.
// SCALE: multiply output row by dis[row]. BIAS: add bias.
template <int COLS, bool SCALE, bool BIAS>
__global__ void k_gemm(const float* __restrict__ A, const float* __restrict__ W,
                       const float* __restrict__ bias, const float* __restrict__ dis,
                       float* __restrict__ out, int M) {
    constexpr int ROWS = 64;
    constexpr int CG   = COLS / 32;
    __shared__ float Ws[32 * COLS];
    __shared__ float Hs[ROWS * 36];

    const int tid  = threadIdx.x;
    const int rl   = tid / CG;
    const int cg   = tid % CG;
    const int row0 = blockIdx.x * ROWS;

    float acc[32];
#pragma unroll
    for (int j = 0; j < 32; j++) acc[j] = 0.f;

    for (int kc = 0; kc < 4; kc++) {
        for (int i = tid * 4; i < 32 * COLS; i += blockDim.x * 4)
            *reinterpret_cast<float4*>(&Ws[i]) =
                *reinterpret_cast<const float4*>(&W[kc * 32 * COLS + i]);
        for (int i = tid; i < ROWS * 8; i += blockDim.x) {
            int r = i >> 3, k4 = (i & 7) * 4;
            int gr = row0 + r;
            float4 v = (gr < M)
                ? *reinterpret_cast<const float4*>(&A[(size_t)gr * 128 + kc * 32 + k4])
                : make_float4(0.f, 0.f, 0.f, 0.f);
            *reinterpret_cast<float4*>(&Hs[r * 36 + k4]) = v;
        }
        __syncthreads();
#pragma unroll
        for (int k = 0; k < 32; k++) {
            float hv = Hs[rl * 36 + k];
#pragma unroll
            for (int j = 0; j < 32; j++)
                acc[j] += hv * Ws[k * COLS + cg * 32 + j];
        }
        __syncthreads();
    }

    int gr = row0 + rl;
    if (gr < M) {
        float sc = SCALE ? dis[gr] : 1.0f;
#pragma unroll
        for (int j = 0; j < 32; j += 4) {
            float4 v;
            v.x = acc[j + 0] * sc;
            v.y = acc[j + 1] * sc;
            v.z = acc[j + 2] * sc;
            v.w = acc[j + 3] * sc;
            if (BIAS) {
                float4 b = *reinterpret_cast<const float4*>(&bias[cg * 32 + j]);
                v.x += b.x; v.y += b.y; v.z += b.z; v.w += b.w;
            }
            *reinterpret_cast<float4*>(&out[(size_t)gr * COLS + cg * 32 + j]) = v;
        }
    }
}

// ---------------------------------------------------------------- aggregation
// One warp per destination node d:
//   out[d] = [relu]( dis[d] * (sum_{s in N(d)} tb[s] + tb[d]) + bias )
template <int COLS, bool RELU>
__global__ void k_agg(const float* __restrict__ tb, const int* __restrict__ rowptr,
                      const int* __restrict__ esrc, const float* __restrict__ dis,
                      const float* __restrict__ bias, float* __restrict__ out, int n) {
    const int warp = (blockIdx.x * blockDim.x + threadIdx.x) >> 5;
    const int lane = threadIdx.x & 31;
    if (warp >= n) return;
    const int beg = __ldg(&rowptr[warp]);
    const int end = __ldg(&rowptr[warp + 1]);

    if constexpr (COLS == 128) {
        float4 acc = *reinterpret_cast<const float4*>(&tb[(size_t)warp * 128 + lane * 4]);
        int e = beg;
        for (; e + 4 <= end; e += 4) {
            int s0 = __ldg(&esrc[e + 0]);
            int s1 = __ldg(&esrc[e + 1]);
            int s2 = __ldg(&esrc[e + 2]);
            int s3 = __ldg(&esrc[e + 3]);
            float4 v0 = *reinterpret_cast<const float4*>(&tb[(size_t)s0 * 128 + lane * 4]);
            float4 v1 = *reinterpret_cast<const float4*>(&tb[(size_t)s1 * 128 + lane * 4]);
            float4 v2 = *reinterpret_cast<const float4*>(&tb[(size_t)s2 * 128 + lane * 4]);
            float4 v3 = *reinterpret_cast<const float4*>(&tb[(size_t)s3 * 128 + lane * 4]);
            acc.x += v0.x + v1.x + v2.x + v3.x;
            acc.y += v0.y + v1.y + v2.y + v3.y;
            acc.z += v0.z + v1.z + v2.z + v3.z;
            acc.w += v0.w + v1.w + v2.w + v3.w;
        }
        for (; e < end; e++) {
            int s = __ldg(&esrc[e]);
            float4 v = *reinterpret_cast<const float4*>(&tb[(size_t)s * 128 + lane * 4]);
            acc.x += v.x; acc.y += v.y; acc.z += v.z; acc.w += v.w;
        }
        float d = dis[warp];
        float4 b = *reinterpret_cast<const float4*>(&bias[lane * 4]);
        float4 r;
        r.x = fmaf(acc.x, d, b.x);
        r.y = fmaf(acc.y, d, b.y);
        r.z = fmaf(acc.z, d, b.z);
        r.w = fmaf(acc.w, d, b.w);
        if (RELU) {
            r.x = fmaxf(r.x, 0.f); r.y = fmaxf(r.y, 0.f);
            r.z = fmaxf(r.z, 0.f); r.w = fmaxf(r.w, 0.f);
        }
        *reinterpret_cast<float4*>(&out[(size_t)warp * 128 + lane * 4]) = r;
    } else {  // COLS == 64, float2 per lane
        float2 acc = *reinterpret_cast<const float2*>(&tb[(size_t)warp * 64 + lane * 2]);
        int e = beg;
        for (; e + 4 <= end; e += 4) {
            int s0 = __ldg(&esrc[e + 0]);
            int s1 = __ldg(&esrc[e + 1]);
            int s2 = __ldg(&esrc[e + 2]);
            int s3 = __ldg(&esrc[e + 3]);
            float2 v0 = *reinterpret_cast<const float2*>(&tb[(size_t)s0 * 64 + lane * 2]);
            float2 v1 = *reinterpret_cast<const float2*>(&tb[(size_t)s1 * 64 + lane * 2]);
            float2 v2 = *reinterpret_cast<const float2*>(&tb[(size_t)s2 * 64 + lane * 2]);
            float2 v3 = *reinterpret_cast<const float2*>(&tb[(size_t)s3 * 64 + lane * 2]);
            acc.x += v0.x + v1.x + v2.x + v3.x;
            acc.y += v0.y + v1.y + v2.y + v3.y;
        }
        for (; e < end; e++) {
            int s = __ldg(&esrc[e]);
            float2 v = *reinterpret_cast<const float2*>(&tb[(size_t)s * 64 + lane * 2]);
            acc.x += v.x; acc.y += v.y;
        }
        float d = dis[warp];
        float2 b = *reinterpret_cast<const float2*>(&bias[lane * 2]);
        float2 r;
        r.x = fmaf(acc.x, d, b.x);
        r.y = fmaf(acc.y, d, b.y);
        if (RELU) { r.x = fmaxf(r.x, 0.f); r.y = fmaxf(r.y, 0.f); }
        *reinterpret_cast<float2*>(&out[(size_t)warp * 64 + lane * 2]) = r;
    }
}

// ---------------------------------------------------------------- pool
__global__ void k_pool(const float* __restrict__ h, const int* __restrict__ batch,
                       float* __restrict__ out, int n) {
    int gid = blockIdx.x * blockDim.x + threadIdx.x;
    int node = gid / 16;
    int c = (gid % 16) * 4;
    if (node >= n) return;
    int g = batch[node];
    float4 v = *reinterpret_cast<const float4*>(&h[(size_t)node * 64 + c]);
    float* a = &out[(size_t)g * 64 + c];
    asm volatile("red.global.add.v4.f32 [%0], {%1,%2,%3,%4};"
                 :: "l"(a), "f"(v.x), "f"(v.y), "f"(v.z), "f"(v.w) : "memory");
}

// ---------------------------------------------------------------- launch
extern "C" void kernel_launch(void* const* d_in, const int* in_sizes, int n_in,
                              void* d_out, int out_size) {
    const float* x     = (const float*)d_in[0];
    const int*   ei    = (const int*)  d_in[1];
    const int*   batch = (const int*)  d_in[2];
    const float* W_emb = (const float*)d_in[3];
    const float* b_emb = (const float*)d_in[4];
    const float* W1    = (const float*)d_in[5];
    const float* b1    = (const float*)d_in[6];
    const float* W2    = (const float*)d_in[7];
    const float* b2    = (const float*)d_in[8];
    const float* W3    = (const float*)d_in[9];
    const float* b3    = (const float*)d_in[10];

    const int n = in_sizes[2];
    const int e = in_sizes[1] / 2;
    const int* src = ei;
    const int* dst = ei + e;

    float *dis, *h, *t;
    int *deg, *rowptr, *cursor, *esrc;
    cudaGetSymbolAddress((void**)&dis,    g_dis);
    cudaGetSymbolAddress((void**)&deg,    g_deg);
    cudaGetSymbolAddress((void**)&rowptr, g_rowptr);
    cudaGetSymbolAddress((void**)&cursor, g_cursor);
    cudaGetSymbolAddress((void**)&esrc,   g_esrc);
    cudaGetSymbolAddress((void**)&h,      g_h);
    cudaGetSymbolAddress((void**)&t,      g_t);

    const int TB = 256;
    auto cdiv = [](long long a, long long b) { return (int)((a + b - 1) / b); };

    // --- CSR + normalization prep (once per call) ---
    k_zeroi  <<<cdiv(n, TB), TB>>>(deg, n);
    k_deg    <<<cdiv(e, TB), TB>>>(dst, deg, e);
    k_dis    <<<cdiv(n, TB), TB>>>(deg, dis, n);
    k_scan   <<<1, 1024>>>(deg, rowptr, cursor, n);
    k_permute<<<cdiv(e, TB), TB>>>(src, dst, cursor, esrc, e);

    // --- Embedding: h = x @ W_emb + b_emb ---
    k_gemm<128, false, true><<<cdiv(n, 64), 256>>>(x, W_emb, b_emb, dis, h, n);

    // --- Layer 1 ---
    k_gemm<128, true, false><<<cdiv(n, 64), 256>>>(h, W1, nullptr, dis, t, n);
    k_agg<128, true><<<cdiv(n, 8), 256>>>(t, rowptr, esrc, dis, b1, h, n);

    // --- Layer 2 ---
    k_gemm<128, true, false><<<cdiv(n, 64), 256>>>(h, W2, nullptr, dis, t, n);
    k_agg<128, true><<<cdiv(n, 8), 256>>>(t, rowptr, esrc, dis, b2, h, n);

    // --- Layer 3 (D_OUT = 64, no relu) ---
    k_gemm<64, true, false><<<cdiv(n, 64), 128>>>(h, W3, nullptr, dis, t, n);
    k_agg<64, false><<<cdiv(n, 8), 256>>>(t, rowptr, esrc, dis, b3, h, n);

    // --- Global add pool ---
    k_zero4<<<cdiv(out_size / 4, TB), TB>>>((float*)d_out, out_size / 4);
    k_pool<<<cdiv((long long)n * 16, TB), TB>>>(h, batch, (float*)d_out, n);
}

// round 3
// speedup vs baseline: 1.8391x; 1.0312x over previous
#include <cuda_runtime.h>
#include <cstdint>

#define NMAX  100000
#define EMAX  1600000
#define DHID  128
#define PREP_BLOCKS 128
#define PREP_THREADS 1024

// Scratch (static device globals; allocation is forbidden)
__device__ float g_dis[NMAX];              // deg^{-1/2} (with self loop)
__device__ int   g_deg [NMAX];
__device__ int   g_rowptr[NMAX + 1];
__device__ int   g_cursor[NMAX];
__device__ int   g_esrc[EMAX];             // src ids grouped by dst (CSR)
__device__ float g_h  [NMAX * DHID];       // current features
__device__ float g_t  [NMAX * DHID];       // tb = (h @ W) * dis[row]
__device__ int   g_bsum[PREP_BLOCKS];      // per-block partial sums for scan
__device__ int   g_boff[PREP_BLOCKS];      // exclusive block offsets
__device__ int   g_total;
__device__ unsigned g_bar;                 // grid barrier ticket counter

// ---------------------------------------------------------------- grid sync
__device__ __forceinline__ void grid_sync(int nb) {
    __syncthreads();
    if (threadIdx.x == 0) {
        __threadfence();
        unsigned ticket = atomicAdd(&g_bar, 1u);
        unsigned phase  = ticket / (unsigned)nb + 1u;
        while (atomicAdd(&g_bar, 0u) < phase * (unsigned)nb) { }
    }
    __syncthreads();
}

// ---------------------------------------------------------------- fused prep
// zero(deg, d_out) -> degree count -> dis -> parallel scan -> rowptr/cursor -> permute
__global__ __launch_bounds__(PREP_THREADS, 1)
void k_prep(const int* __restrict__ src, const int* __restrict__ dst, int e, int n,
            float* __restrict__ d_out, int out4) {
    const int tid  = threadIdx.x;
    const int lane = tid & 31, wid = tid >> 5;
    const int T    = PREP_BLOCKS * PREP_THREADS;
    const int gtid = blockIdx.x * PREP_THREADS + tid;
    __shared__ int sh[32];
    __shared__ int s_boff;

    // phase 0: zero deg and d_out
    for (int i = gtid; i < n; i += T) g_deg[i] = 0;
    float4* o4 = reinterpret_cast<float4*>(d_out);
    for (int i = gtid; i < out4; i += T) o4[i] = make_float4(0.f, 0.f, 0.f, 0.f);
    grid_sync(PREP_BLOCKS);

    // phase 1: degree histogram
    for (int i = gtid; i < e; i += T) atomicAdd(&g_deg[dst[i]], 1);
    grid_sync(PREP_BLOCKS);

    // phase 2: dis + per-thread chunk sums -> block partial sum
    for (int i = gtid; i < n; i += T) g_dis[i] = rsqrtf((float)g_deg[i] + 1.0f);

    const int per = (n + T - 1) / T;          // contiguous chunk per thread
    const int cb  = gtid * per;
    const int ce  = min(cb + per, n);
    int csum = 0;
    for (int i = cb; i < ce; i++) csum += g_deg[i];

    // block-level exclusive scan of per-thread sums
    int x = csum;
#pragma unroll
    for (int o = 1; o < 32; o <<= 1) {
        int y = __shfl_up_sync(0xffffffffu, x, o);
        if (lane >= o) x += y;
    }
    if (lane == 31) sh[wid] = x;
    __syncthreads();
    if (wid == 0) {
        int w = sh[lane];
        int xx = w;
#pragma unroll
        for (int o = 1; o < 32; o <<= 1) {
            int y = __shfl_up_sync(0xffffffffu, xx, o);
            if (lane >= o) xx += y;
        }
        sh[lane] = xx - w;                    // exclusive warp offset
        if (lane == 31) g_bsum[blockIdx.x] = xx;  // block total
    }
    __syncthreads();
    const int thr_excl = x - csum + sh[wid];  // exclusive within block
    grid_sync(PREP_BLOCKS);

    // phase 3: block 0 scans the 128 block totals
    if (blockIdx.x == 0 && wid == 0) {
#pragma unroll
        for (int base = 0; base < PREP_BLOCKS; base += 32) {
            // sequential-carry warp scan over 4 groups of 32
            ;
        }
        int carry = 0;
        for (int base = 0; base < PREP_BLOCKS; base += 32) {
            int v = g_bsum[base + lane];
            int s = v;
#pragma unroll
            for (int o = 1; o < 32; o <<= 1) {
                int y = __shfl_up_sync(0xffffffffu, s, o);
                if (lane >= o) s += y;
            }
            g_boff[base + lane] = s - v + carry;
            carry += __shfl_sync(0xffffffffu, s, 31);
        }
        if (lane == 0) g_total = carry;
    }
    grid_sync(PREP_BLOCKS);

    // phase 4: write rowptr / cursor
    if (tid == 0) s_boff = g_boff[blockIdx.x];
    __syncthreads();
    int run = s_boff + thr_excl;
    for (int i = cb; i < ce; i++) {
        g_rowptr[i] = run;
        g_cursor[i] = run;
        run += g_deg[i];
    }
    if (gtid == 0) g_rowptr[n] = g_total;
    grid_sync(PREP_BLOCKS);

    // phase 5: permute edges into CSR order
    for (int i = gtid; i < e; i += T) {
        int pos = atomicAdd(&g_cursor[dst[i]], 1);
        g_esrc[pos] = src[i];
    }
}

// ---------------------------------------------------------------- GEMM
// A: [M,128] row-major, W: [128,COLS] row-major, out: [M,COLS].
template <int COLS, bool SCALE, bool BIAS>
__global__ void k_gemm(const float* __restrict__ A, const float* __restrict__ W,
                       const float* __restrict__ bias, const float* __restrict__ dis,
                       float* __restrict__ out, int M) {
    constexpr int ROWS = 64;
    constexpr int CG   = COLS / 32;
    __shared__ float Ws[32 * COLS];
    __shared__ float Hs[ROWS * 36];

    const int tid  = threadIdx.x;
    const int rl   = tid / CG;
    const int cg   = tid % CG;
    const int row0 = blockIdx.x * ROWS;

    float acc[32];
#pragma unroll
    for (int j = 0; j < 32; j++) acc[j] = 0.f;

    for (int kc = 0; kc < 4; kc++) {
        for (int i = tid * 4; i < 32 * COLS; i += blockDim.x * 4)
            *reinterpret_cast<float4*>(&Ws[i]) =
                *reinterpret_cast<const float4*>(&W[kc * 32 * COLS + i]);
        for (int i = tid; i < ROWS * 8; i += blockDim.x) {
            int r = i >> 3, k4 = (i & 7) * 4;
            int gr = row0 + r;
            float4 v = (gr < M)
                ? *reinterpret_cast<const float4*>(&A[(size_t)gr * 128 + kc * 32 + k4])
                : make_float4(0.f, 0.f, 0.f, 0.f);
            *reinterpret_cast<float4*>(&Hs[r * 36 + k4]) = v;
        }
        __syncthreads();
#pragma unroll
        for (int k = 0; k < 32; k++) {
            float hv = Hs[rl * 36 + k];
#pragma unroll
            for (int j = 0; j < 32; j++)
                acc[j] += hv * Ws[k * COLS + cg * 32 + j];
        }
        __syncthreads();
    }

    int gr = row0 + rl;
    if (gr < M) {
        float sc = SCALE ? dis[gr] : 1.0f;
#pragma unroll
        for (int j = 0; j < 32; j += 4) {
            float4 v;
            v.x = acc[j + 0] * sc;
            v.y = acc[j + 1] * sc;
            v.z = acc[j + 2] * sc;
            v.w = acc[j + 3] * sc;
            if (BIAS) {
                float4 b = *reinterpret_cast<const float4*>(&bias[cg * 32 + j]);
                v.x += b.x; v.y += b.y; v.z += b.z; v.w += b.w;
            }
            *reinterpret_cast<float4*>(&out[(size_t)gr * COLS + cg * 32 + j]) = v;
        }
    }
}

// ---------------------------------------------------------------- aggregation
// One warp per destination node d:
//   out[d] = [relu]( dis[d] * (sum_{s in N(d)} tb[s] + tb[d]) + bias )
template <int COLS, bool RELU>
__global__ void k_agg(const float* __restrict__ tb, const int* __restrict__ rowptr,
                      const int* __restrict__ esrc, const float* __restrict__ dis,
                      const float* __restrict__ bias, float* __restrict__ out, int n) {
    const int warp = (blockIdx.x * blockDim.x + threadIdx.x) >> 5;
    const int lane = threadIdx.x & 31;
    if (warp >= n) return;
    const int beg = __ldg(&rowptr[warp]);
    const int end = __ldg(&rowptr[warp + 1]);

    if constexpr (COLS == 128) {
        float4 acc = *reinterpret_cast<const float4*>(&tb[(size_t)warp * 128 + lane * 4]);
        int e = beg;
        for (; e + 8 <= end; e += 8) {
            int s[8];
#pragma unroll
            for (int u = 0; u < 8; u++) s[u] = __ldg(&esrc[e + u]);
            float4 v[8];
#pragma unroll
            for (int u = 0; u < 8; u++)
                v[u] = *reinterpret_cast<const float4*>(&tb[(size_t)s[u] * 128 + lane * 4]);
#pragma unroll
            for (int u = 0; u < 8; u++) {
                acc.x += v[u].x; acc.y += v[u].y; acc.z += v[u].z; acc.w += v[u].w;
            }
        }
        for (; e < end; e++) {
            int s = __ldg(&esrc[e]);
            float4 v = *reinterpret_cast<const float4*>(&tb[(size_t)s * 128 + lane * 4]);
            acc.x += v.x; acc.y += v.y; acc.z += v.z; acc.w += v.w;
        }
        float d = dis[warp];
        float4 b = *reinterpret_cast<const float4*>(&bias[lane * 4]);
        float4 r;
        r.x = fmaf(acc.x, d, b.x);
        r.y = fmaf(acc.y, d, b.y);
        r.z = fmaf(acc.z, d, b.z);
        r.w = fmaf(acc.w, d, b.w);
        if (RELU) {
            r.x = fmaxf(r.x, 0.f); r.y = fmaxf(r.y, 0.f);
            r.z = fmaxf(r.z, 0.f); r.w = fmaxf(r.w, 0.f);
        }
        *reinterpret_cast<float4*>(&out[(size_t)warp * 128 + lane * 4]) = r;
    } else {  // COLS == 64
        float2 acc = *reinterpret_cast<const float2*>(&tb[(size_t)warp * 64 + lane * 2]);
        int e = beg;
        for (; e + 8 <= end; e += 8) {
            int s[8];
#pragma unroll
            for (int u = 0; u < 8; u++) s[u] = __ldg(&esrc[e + u]);
            float2 v[8];
#pragma unroll
            for (int u = 0; u < 8; u++)
                v[u] = *reinterpret_cast<const float2*>(&tb[(size_t)s[u] * 64 + lane * 2]);
#pragma unroll
            for (int u = 0; u < 8; u++) { acc.x += v[u].x; acc.y += v[u].y; }
        }
        for (; e < end; e++) {
            int s = __ldg(&esrc[e]);
            float2 v = *reinterpret_cast<const float2*>(&tb[(size_t)s * 64 + lane * 2]);
            acc.x += v.x; acc.y += v.y;
        }
        float d = dis[warp];
        float2 b = *reinterpret_cast<const float2*>(&bias[lane * 2]);
        float2 r;
        r.x = fmaf(acc.x, d, b.x);
        r.y = fmaf(acc.y, d, b.y);
        if (RELU) { r.x = fmaxf(r.x, 0.f); r.y = fmaxf(r.y, 0.f); }
        *reinterpret_cast<float2*>(&out[(size_t)warp * 64 + lane * 2]) = r;
    }
}

// ---------------------------------------------------------------- pool
__global__ void k_pool(const float* __restrict__ h, const int* __restrict__ batch,
                       float* __restrict__ out, int n) {
    int gid = blockIdx.x * blockDim.x + threadIdx.x;
    int node = gid / 16;
    int c = (gid % 16) * 4;
    if (node >= n) return;
    int g = batch[node];
    float4 v = *reinterpret_cast<const float4*>(&h[(size_t)node * 64 + c]);
    float* a = &out[(size_t)g * 64 + c];
    asm volatile("red.global.add.v4.f32 [%0], {%1,%2,%3,%4};"
                 :: "l"(a), "f"(v.x), "f"(v.y), "f"(v.z), "f"(v.w) : "memory");
}

// ---------------------------------------------------------------- launch
extern "C" void kernel_launch(void* const* d_in, const int* in_sizes, int n_in,
                              void* d_out, int out_size) {
    const float* x     = (const float*)d_in[0];
    const int*   ei    = (const int*)  d_in[1];
    const int*   batch = (const int*)  d_in[2];
    const float* W_emb = (const float*)d_in[3];
    const float* b_emb = (const float*)d_in[4];
    const float* W1    = (const float*)d_in[5];
    const float* b1    = (const float*)d_in[6];
    const float* W2    = (const float*)d_in[7];
    const float* b2    = (const float*)d_in[8];
    const float* W3    = (const float*)d_in[9];
    const float* b3    = (const float*)d_in[10];

    const int n = in_sizes[2];
    const int e = in_sizes[1] / 2;
    const int* src = ei;
    const int* dst = ei + e;

    float *dis, *h, *t;
    int *rowptr, *esrc;
    cudaGetSymbolAddress((void**)&dis,    g_dis);
    cudaGetSymbolAddress((void**)&rowptr, g_rowptr);
    cudaGetSymbolAddress((void**)&esrc,   g_esrc);
    cudaGetSymbolAddress((void**)&h,      g_h);
    cudaGetSymbolAddress((void**)&t,      g_t);

    auto cdiv = [](long long a, long long b) { return (int)((a + b - 1) / b); };

    // 0: fused prep (CSR + dis + zero d_out)
    k_prep<<<PREP_BLOCKS, PREP_THREADS>>>(src, dst, e, n, (float*)d_out, out_size / 4);

    // 1: embedding  h = x @ W_emb + b_emb
    k_gemm<128, false, true><<<cdiv(n, 64), 256>>>(x, W_emb, b_emb, dis, h, n);

    // 2: layer-1 GEMM  t = (h @ W1) * dis
    k_gemm<128, true, false><<<cdiv(n, 64), 256>>>(h, W1, nullptr, dis, t, n);

    // 3: layer-1 aggregation  (<- profiled slot)
    k_agg<128, true><<<cdiv(n, 8), 256>>>(t, rowptr, esrc, dis, b1, h, n);

    // 4-5: layer 2
    k_gemm<128, true, false><<<cdiv(n, 64), 256>>>(h, W2, nullptr, dis, t, n);
    k_agg<128, true><<<cdiv(n, 8), 256>>>(t, rowptr, esrc, dis, b2, h, n);

    // 6-7: layer 3 (D_OUT = 64, no relu)
    k_gemm<64, true, false><<<cdiv(n, 64), 128>>>(h, W3, nullptr, dis, t, n);
    k_agg<64, false><<<cdiv(n, 8), 256>>>(t, rowptr, esrc, dis, b3, h, n);

    // 8: pool (d_out zeroed by prep)
    k_pool<<<cdiv((long long)n * 16, 256), 256>>>(h, batch, (float*)d_out, n);
}

// round 4
// speedup vs baseline: 9.1049x; 4.9508x over previous
#include <cuda_runtime.h>
#include <cstdint>

#define NMAX  100000
#define EMAX  1600000
#define DHID  128
#define PREP_BLOCKS 128
#define PREP_THREADS 1024

// Scratch (static device globals; allocation is forbidden)
__device__ float g_dis[NMAX];
__device__ int   g_deg [NMAX];
__device__ int   g_rowptr[NMAX + 1];
__device__ int   g_cursor[NMAX];
__device__ int   g_esrc[EMAX];
__device__ float g_h  [NMAX * DHID];
__device__ float g_t  [NMAX * DHID];
__device__ int   g_bsum[PREP_BLOCKS];
__device__ int   g_boff[PREP_BLOCKS];
__device__ int   g_total;
__device__ unsigned g_bar;

// ---------------------------------------------------------------- grid sync
__device__ __forceinline__ void grid_sync(int nb) {
    __syncthreads();
    if (threadIdx.x == 0) {
        __threadfence();
        unsigned ticket = atomicAdd(&g_bar, 1u);
        unsigned phase  = ticket / (unsigned)nb + 1u;
        while (atomicAdd(&g_bar, 0u) < phase * (unsigned)nb) { }
    }
    __syncthreads();
}

// ---------------------------------------------------------------- fused prep
__global__ __launch_bounds__(PREP_THREADS, 1)
void k_prep(const int* __restrict__ src, const int* __restrict__ dst, int e, int n) {
    const int tid  = threadIdx.x;
    const int lane = tid & 31, wid = tid >> 5;
    const int T    = PREP_BLOCKS * PREP_THREADS;
    const int gtid = blockIdx.x * PREP_THREADS + tid;
    __shared__ int sh[32];
    __shared__ int s_boff;

    for (int i = gtid; i < n; i += T) g_deg[i] = 0;
    grid_sync(PREP_BLOCKS);

    for (int i = gtid; i < e; i += T) atomicAdd(&g_deg[dst[i]], 1);
    grid_sync(PREP_BLOCKS);

    for (int i = gtid; i < n; i += T) g_dis[i] = rsqrtf((float)g_deg[i] + 1.0f);

    const int per = (n + T - 1) / T;
    const int cb  = gtid * per;
    const int ce  = min(cb + per, n);
    int csum = 0;
    for (int i = cb; i < ce; i++) csum += g_deg[i];

    int x = csum;
#pragma unroll
    for (int o = 1; o < 32; o <<= 1) {
        int y = __shfl_up_sync(0xffffffffu, x, o);
        if (lane >= o) x += y;
    }
    if (lane == 31) sh[wid] = x;
    __syncthreads();
    if (wid == 0) {
        int w = sh[lane];
        int xx = w;
#pragma unroll
        for (int o = 1; o < 32; o <<= 1) {
            int y = __shfl_up_sync(0xffffffffu, xx, o);
            if (lane >= o) xx += y;
        }
        sh[lane] = xx - w;
        if (lane == 31) g_bsum[blockIdx.x] = xx;
    }
    __syncthreads();
    const int thr_excl = x - csum + sh[wid];
    grid_sync(PREP_BLOCKS);

    if (blockIdx.x == 0 && wid == 0) {
        int carry = 0;
        for (int base = 0; base < PREP_BLOCKS; base += 32) {
            int v = g_bsum[base + lane];
            int s = v;
#pragma unroll
            for (int o = 1; o < 32; o <<= 1) {
                int y = __shfl_up_sync(0xffffffffu, s, o);
                if (lane >= o) s += y;
            }
            g_boff[base + lane] = s - v + carry;
            carry += __shfl_sync(0xffffffffu, s, 31);
        }
        if (lane == 0) g_total = carry;
    }
    grid_sync(PREP_BLOCKS);

    if (tid == 0) s_boff = g_boff[blockIdx.x];
    __syncthreads();
    int run = s_boff + thr_excl;
    for (int i = cb; i < ce; i++) {
        g_rowptr[i] = run;
        g_cursor[i] = run;
        run += g_deg[i];
    }
    if (gtid == 0) g_rowptr[n] = g_total;
    grid_sync(PREP_BLOCKS);

    for (int i = gtid; i < e; i += T) {
        int pos = atomicAdd(&g_cursor[dst[i]], 1);
        g_esrc[pos] = src[i];
    }
}

__global__ void k_zero4(float* p, int n4) {
    int i = blockIdx.x * blockDim.x + threadIdx.x;
    if (i < n4) reinterpret_cast<float4*>(p)[i] = make_float4(0.f, 0.f, 0.f, 0.f);
}

// ---------------------------------------------------------------- GEMM
// Register-tiled SGEMM. A: [M,128] row-major, W: [128,BN] row-major, out: [M,BN].
// Block tile 128xBN, thread tile 8x8, BK=16, double-buffered smem.
template <int BN, bool SCALE, bool BIAS>
__global__ void k_gemm(const float* __restrict__ A, const float* __restrict__ W,
                       const float* __restrict__ bias, const float* __restrict__ dis,
                       float* __restrict__ out, int M) {
    constexpr int BM = 128, BK = 16;
    constexpr int TN = BN / 8;          // threads along n
    constexpr int TM = BM / 8;          // 16
    constexpr int T  = TN * TM;         // 256 (BN=128) / 128 (BN=64)
    constexpr int A_PER = (BM * BK / 4) / T;   // float4 per thread for A tile
    constexpr int W_PER = (BK * BN / 4) / T;   // float4 per thread for W tile
    constexpr int NKT = 128 / BK;       // 8 k-tiles

    __shared__ float As[2][BK][BM];
    __shared__ float Ws[2][BK][BN];

    const int tid = threadIdx.x;
    const int tn  = tid % TN;
    const int tm  = tid / TN;
    const int row0 = blockIdx.x * BM;

    float acc[8][8];
#pragma unroll
    for (int i = 0; i < 8; i++)
#pragma unroll
        for (int j = 0; j < 8; j++) acc[i][j] = 0.f;

    float4 rA[A_PER], rW[W_PER];

    // ---- prologue: load k-tile 0 ----
#pragma unroll
    for (int j = 0; j < A_PER; j++) {
        int i = tid + j * T;
        int m = i >> 2, kq = i & 3;
        int gr = row0 + m; if (gr >= M) gr = M - 1;
        rA[j] = *reinterpret_cast<const float4*>(&A[(size_t)gr * 128 + kq * 4]);
    }
#pragma unroll
    for (int j = 0; j < W_PER; j++) {
        int i = tid + j * T;
        int k = i / (BN / 4), c = i % (BN / 4);
        rW[j] = *reinterpret_cast<const float4*>(&W[(size_t)k * BN + c * 4]);
    }
#pragma unroll
    for (int j = 0; j < A_PER; j++) {
        int i = tid + j * T;
        int m = i >> 2, kq = i & 3;
        As[0][kq * 4 + 0][m] = rA[j].x;
        As[0][kq * 4 + 1][m] = rA[j].y;
        As[0][kq * 4 + 2][m] = rA[j].z;
        As[0][kq * 4 + 3][m] = rA[j].w;
    }
#pragma unroll
    for (int j = 0; j < W_PER; j++) {
        int i = tid + j * T;
        int k = i / (BN / 4), c = i % (BN / 4);
        *reinterpret_cast<float4*>(&Ws[0][k][c * 4]) = rW[j];
    }
    __syncthreads();

    int buf = 0;
    for (int kt = 0; kt < NKT; kt++) {
        if (kt < NKT - 1) {
            const int k0 = (kt + 1) * BK;
#pragma unroll
            for (int j = 0; j < A_PER; j++) {
                int i = tid + j * T;
                int m = i >> 2, kq = i & 3;
                int gr = row0 + m; if (gr >= M) gr = M - 1;
                rA[j] = *reinterpret_cast<const float4*>(&A[(size_t)gr * 128 + k0 + kq * 4]);
            }
#pragma unroll
            for (int j = 0; j < W_PER; j++) {
                int i = tid + j * T;
                int k = i / (BN / 4), c = i % (BN / 4);
                rW[j] = *reinterpret_cast<const float4*>(&W[(size_t)(k0 + k) * BN + c * 4]);
            }
        }
#pragma unroll
        for (int k = 0; k < BK; k++) {
            float a[8], b[8];
            *reinterpret_cast<float4*>(&a[0]) = *reinterpret_cast<float4*>(&As[buf][k][tm * 8 + 0]);
            *reinterpret_cast<float4*>(&a[4]) = *reinterpret_cast<float4*>(&As[buf][k][tm * 8 + 4]);
            *reinterpret_cast<float4*>(&b[0]) = *reinterpret_cast<float4*>(&Ws[buf][k][tn * 8 + 0]);
            *reinterpret_cast<float4*>(&b[4]) = *reinterpret_cast<float4*>(&Ws[buf][k][tn * 8 + 4]);
#pragma unroll
            for (int i = 0; i < 8; i++)
#pragma unroll
                for (int j = 0; j < 8; j++)
                    acc[i][j] = fmaf(a[i], b[j], acc[i][j]);
        }
        if (kt < NKT - 1) {
            int nb = buf ^ 1;
#pragma unroll
            for (int j = 0; j < A_PER; j++) {
                int i = tid + j * T;
                int m = i >> 2, kq = i & 3;
                As[nb][kq * 4 + 0][m] = rA[j].x;
                As[nb][kq * 4 + 1][m] = rA[j].y;
                As[nb][kq * 4 + 2][m] = rA[j].z;
                As[nb][kq * 4 + 3][m] = rA[j].w;
            }
#pragma unroll
            for (int j = 0; j < W_PER; j++) {
                int i = tid + j * T;
                int k = i / (BN / 4), c = i % (BN / 4);
                *reinterpret_cast<float4*>(&Ws[nb][k][c * 4]) = rW[j];
            }
            __syncthreads();
            buf = nb;
        }
    }

    // ---- epilogue ----
    float bv[8];
    if (BIAS) {
        *reinterpret_cast<float4*>(&bv[0]) = *reinterpret_cast<const float4*>(&bias[tn * 8 + 0]);
        *reinterpret_cast<float4*>(&bv[4]) = *reinterpret_cast<const float4*>(&bias[tn * 8 + 4]);
    }
#pragma unroll
    for (int i = 0; i < 8; i++) {
        int gr = row0 + tm * 8 + i;
        if (gr < M) {
            float sc = SCALE ? dis[gr] : 1.0f;
#pragma unroll
            for (int j = 0; j < 8; j += 4) {
                float4 v;
                v.x = acc[i][j + 0] * sc;
                v.y = acc[i][j + 1] * sc;
                v.z = acc[i][j + 2] * sc;
                v.w = acc[i][j + 3] * sc;
                if (BIAS) { v.x += bv[j]; v.y += bv[j + 1]; v.z += bv[j + 2]; v.w += bv[j + 3]; }
                *reinterpret_cast<float4*>(&out[(size_t)gr * BN + tn * 8 + j]) = v;
            }
        }
    }
}

// ---------------------------------------------------------------- aggregation
template <int COLS, bool RELU>
__global__ void k_agg(const float* __restrict__ tb, const int* __restrict__ rowptr,
                      const int* __restrict__ esrc, const float* __restrict__ dis,
                      const float* __restrict__ bias, float* __restrict__ out, int n) {
    const int warp = (blockIdx.x * blockDim.x + threadIdx.x) >> 5;
    const int lane = threadIdx.x & 31;
    if (warp >= n) return;
    const int beg = __ldg(&rowptr[warp]);
    const int end = __ldg(&rowptr[warp + 1]);

    if constexpr (COLS == 128) {
        float4 acc = *reinterpret_cast<const float4*>(&tb[(size_t)warp * 128 + lane * 4]);
        int e = beg;
        for (; e + 8 <= end; e += 8) {
            int s[8];
#pragma unroll
            for (int u = 0; u < 8; u++) s[u] = __ldg(&esrc[e + u]);
            float4 v[8];
#pragma unroll
            for (int u = 0; u < 8; u++)
                v[u] = *reinterpret_cast<const float4*>(&tb[(size_t)s[u] * 128 + lane * 4]);
#pragma unroll
            for (int u = 0; u < 8; u++) {
                acc.x += v[u].x; acc.y += v[u].y; acc.z += v[u].z; acc.w += v[u].w;
            }
        }
        for (; e < end; e++) {
            int s = __ldg(&esrc[e]);
            float4 v = *reinterpret_cast<const float4*>(&tb[(size_t)s * 128 + lane * 4]);
            acc.x += v.x; acc.y += v.y; acc.z += v.z; acc.w += v.w;
        }
        float d = dis[warp];
        float4 b = *reinterpret_cast<const float4*>(&bias[lane * 4]);
        float4 r;
        r.x = fmaf(acc.x, d, b.x);
        r.y = fmaf(acc.y, d, b.y);
        r.z = fmaf(acc.z, d, b.z);
        r.w = fmaf(acc.w, d, b.w);
        if (RELU) {
            r.x = fmaxf(r.x, 0.f); r.y = fmaxf(r.y, 0.f);
            r.z = fmaxf(r.z, 0.f); r.w = fmaxf(r.w, 0.f);
        }
        *reinterpret_cast<float4*>(&out[(size_t)warp * 128 + lane * 4]) = r;
    } else {
        float2 acc = *reinterpret_cast<const float2*>(&tb[(size_t)warp * 64 + lane * 2]);
        int e = beg;
        for (; e + 8 <= end; e += 8) {
            int s[8];
#pragma unroll
            for (int u = 0; u < 8; u++) s[u] = __ldg(&esrc[e + u]);
            float2 v[8];
#pragma unroll
            for (int u = 0; u < 8; u++)
                v[u] = *reinterpret_cast<const float2*>(&tb[(size_t)s[u] * 64 + lane * 2]);
#pragma unroll
            for (int u = 0; u < 8; u++) { acc.x += v[u].x; acc.y += v[u].y; }
        }
        for (; e < end; e++) {
            int s = __ldg(&esrc[e]);
            float2 v = *reinterpret_cast<const float2*>(&tb[(size_t)s * 64 + lane * 2]);
            acc.x += v.x; acc.y += v.y;
        }
        float d = dis[warp];
        float2 b = *reinterpret_cast<const float2*>(&bias[lane * 2]);
        float2 r;
        r.x = fmaf(acc.x, d, b.x);
        r.y = fmaf(acc.y, d, b.y);
        if (RELU) { r.x = fmaxf(r.x, 0.f); r.y = fmaxf(r.y, 0.f); }
        *reinterpret_cast<float2*>(&out[(size_t)warp * 64 + lane * 2]) = r;
    }
}

// ---------------------------------------------------------------- pool
__global__ void k_pool(const float* __restrict__ h, const int* __restrict__ batch,
                       float* __restrict__ out, int n) {
    int gid = blockIdx.x * blockDim.x + threadIdx.x;
    int node = gid / 16;
    int c = (gid % 16) * 4;
    if (node >= n) return;
    int g = batch[node];
    float4 v = *reinterpret_cast<const float4*>(&h[(size_t)node * 64 + c]);
    float* a = &out[(size_t)g * 64 + c];
    asm volatile("red.global.add.v4.f32 [%0], {%1,%2,%3,%4};"
                 :: "l"(a), "f"(v.x), "f"(v.y), "f"(v.z), "f"(v.w) : "memory");
}

// ---------------------------------------------------------------- launch
extern "C" void kernel_launch(void* const* d_in, const int* in_sizes, int n_in,
                              void* d_out, int out_size) {
    const float* x     = (const float*)d_in[0];
    const int*   ei    = (const int*)  d_in[1];
    const int*   batch = (const int*)  d_in[2];
    const float* W_emb = (const float*)d_in[3];
    const float* b_emb = (const float*)d_in[4];
    const float* W1    = (const float*)d_in[5];
    const float* b1    = (const float*)d_in[6];
    const float* W2    = (const float*)d_in[7];
    const float* b2    = (const float*)d_in[8];
    const float* W3    = (const float*)d_in[9];
    const float* b3    = (const float*)d_in[10];

    const int n = in_sizes[2];
    const int e = in_sizes[1] / 2;
    const int* src = ei;
    const int* dst = ei + e;

    float *dis, *h, *t;
    int *rowptr, *esrc;
    cudaGetSymbolAddress((void**)&dis,    g_dis);
    cudaGetSymbolAddress((void**)&rowptr, g_rowptr);
    cudaGetSymbolAddress((void**)&esrc,   g_esrc);
    cudaGetSymbolAddress((void**)&h,      g_h);
    cudaGetSymbolAddress((void**)&t,      g_t);

    auto cdiv = [](long long a, long long b) { return (int)((a + b - 1) / b); };

    // 0: fused prep (CSR + dis)
    k_prep<<<PREP_BLOCKS, PREP_THREADS>>>(src, dst, e, n);
    // 1: zero d_out
    k_zero4<<<cdiv(out_size / 4, 256), 256>>>((float*)d_out, out_size / 4);
    // 2: embedding  h = x @ W_emb + b_emb
    k_gemm<128, false, true><<<cdiv(n, 128), 256>>>(x, W_emb, b_emb, dis, h, n);
    // 3: layer-1 GEMM  t = (h @ W1) * dis   (<- profiled slot)
    k_gemm<128, true, false><<<cdiv(n, 128), 256>>>(h, W1, nullptr, dis, t, n);
    // 4: layer-1 agg
    k_agg<128, true><<<cdiv(n, 8), 256>>>(t, rowptr, esrc, dis, b1, h, n);
    // 5-6: layer 2
    k_gemm<128, true, false><<<cdiv(n, 128), 256>>>(h, W2, nullptr, dis, t, n);
    k_agg<128, true><<<cdiv(n, 8), 256>>>(t, rowptr, esrc, dis, b2, h, n);
    // 7-8: layer 3 (D_OUT = 64, no relu)
    k_gemm<64, true, false><<<cdiv(n, 128), 128>>>(h, W3, nullptr, dis, t, n);
    k_agg<64, false><<<cdiv(n, 8), 256>>>(t, rowptr, esrc, dis, b3, h, n);
    // 9: pool
    k_pool<<<cdiv((long long)n * 16, 256), 256>>>(h, batch, (float*)d_out, n);
}